// round 1
// baseline (speedup 1.0000x reference)
#include <cuda_runtime.h>

#define D 256
#define P 8
#define B_GR 128
#define N_NODES 50000
#define N_EDGES 300000
#define NPB 16
#define EPB 16

// Scratch (static device globals: allocation-free per harness rules)
__device__ float g_Wpt[P * D * D];        // W_node_props transposed: [p][e][d] = W[p][d][e]
__device__ float g_Wet[D * D];            // W_edge transposed: [k][d] = W_edge[d][k]
__device__ float g_Weff[B_GR * D * D];    // per-graph effective matrix, [b][e][d]
__device__ float g_state_logits[N_NODES];
__device__ float g_rel_logits[N_NODES];

// ---------- packed f32x2 helpers (Blackwell fma.rn.f32x2) ----------
__device__ __forceinline__ unsigned long long pack_f2(float lo, float hi) {
    unsigned long long r;
    asm("mov.b64 %0, {%1, %2};" : "=l"(r) : "f"(lo), "f"(hi));
    return r;
}
__device__ __forceinline__ void fma2(unsigned long long& acc, unsigned long long a,
                                     unsigned long long b) {
    asm("fma.rn.f32x2 %0, %1, %2, %0;" : "+l"(acc) : "l"(a), "l"(b));
}
__device__ __forceinline__ float hsum2(unsigned long long v) {
    float lo, hi;
    asm("mov.b64 {%0, %1}, %2;" : "=f"(lo), "=f"(hi) : "l"(v));
    return lo + hi;
}
__device__ __forceinline__ float elu1(float x) { return x > 0.f ? x : expm1f(x); }

// ---------- prep: transposes ----------
__global__ void prep_kernel(const float* __restrict__ Wnp, const float* __restrict__ We) {
    int tid = blockIdx.x * blockDim.x + threadIdx.x;
    if (tid < P * D * D) {
        int p = tid >> 16;
        int rem = tid & 0xFFFF;
        int e = rem >> 8;
        int d = rem & 0xFF;
        g_Wpt[tid] = Wnp[p * (D * D) + d * D + e];
    } else if (tid < P * D * D + D * D) {
        int r = tid - P * D * D;
        int k = r >> 8;
        int d = r & 0xFF;
        g_Wet[r] = We[d * D + k];
    }
}

// ---------- W_eff[b] = sum_p sim[b][p] * Wpt[p] ----------
__global__ void __launch_bounds__(256) weff_kernel(const float* __restrict__ sim) {
    __shared__ float wpt_s[P][256];
    __shared__ float sim_s[B_GR * P];
    const int t = threadIdx.x;
    const int base = blockIdx.x * 256;  // flat (e,d) chunk
#pragma unroll
    for (int p = 0; p < P; p++) wpt_s[p][t] = g_Wpt[p * (D * D) + base + t];
    for (int i = t; i < B_GR * P; i += 256) sim_s[i] = sim[i];
    __syncthreads();
    for (int b = 0; b < B_GR; b++) {
        float a = 0.f;
#pragma unroll
        for (int p = 0; p < P; p++) a = fmaf(sim_s[b * P + p], wpt_s[p][t], a);
        g_Weff[(size_t)b * (D * D) + base + t] = a;
    }
}

__global__ void zero_kernel() {
    int i = blockIdx.x * blockDim.x + threadIdx.x;
    if (i < N_NODES) g_rel_logits[i] = 0.f;
}

// ---------- node pass: state_logits ----------
__global__ void __launch_bounds__(256) node_kernel(const float* __restrict__ node_attrs,
                                                   const int* __restrict__ node_indices,
                                                   const float* __restrict__ instr,
                                                   const float* __restrict__ w_node) {
    __shared__ __align__(16) float attr_s[NPB][D];
    __shared__ int b_s[NPB];
    __shared__ float red[NPB][8];
    const int d = threadIdx.x;
    const int i0 = blockIdx.x * NPB;
    const int total = min(NPB, N_NODES - i0);
    for (int j = 0; j < total; j++) attr_s[j][d] = node_attrs[(size_t)(i0 + j) * D + d];
    if (d < total) b_s[d] = node_indices[i0 + d];
    __syncthreads();
    const float wn = w_node[d];
    int s = 0;
    while (s < total) {
        const int b = b_s[s];
        int e2 = s + 1;
        while (e2 < total && b_s[e2] == b) e2++;
        const int cnt = e2 - s;
        const float* __restrict__ W = g_Weff + (size_t)b * (D * D) + d;
        float accf[NPB];
        if (cnt == NPB) {
            // fast path: full tile, single graph (s == 0 here)
            unsigned long long acc[NPB];
#pragma unroll
            for (int j = 0; j < NPB; j++) acc[j] = 0ull;
            for (int k = 0; k < D; k += 4) {
                float w0 = __ldg(W + (size_t)k * D);
                float w1 = __ldg(W + (size_t)(k + 1) * D);
                float w2 = __ldg(W + (size_t)(k + 2) * D);
                float w3 = __ldg(W + (size_t)(k + 3) * D);
                unsigned long long wp01 = pack_f2(w0, w1);
                unsigned long long wp23 = pack_f2(w2, w3);
#pragma unroll
                for (int j = 0; j < NPB; j++) {
                    const unsigned long long* ap =
                        reinterpret_cast<const unsigned long long*>(&attr_s[j][k]);
                    fma2(acc[j], ap[0], wp01);
                    fma2(acc[j], ap[1], wp23);
                }
            }
#pragma unroll
            for (int j = 0; j < NPB; j++) accf[j] = hsum2(acc[j]);
        } else {
            // rare: graph boundary inside the tile
            for (int j = 0; j < cnt; j++) accf[j] = 0.f;
            for (int k = 0; k < D; k++) {
                float w = __ldg(W + (size_t)k * D);
                for (int j = 0; j < cnt; j++) accf[j] = fmaf(attr_s[s + j][k], w, accf[j]);
            }
        }
        const float ib = instr[b * D + d];
        for (int j = 0; j < cnt; j++) {
            float t = ib * accf[j];
            float v = wn * elu1(t);
#pragma unroll
            for (int o = 16; o > 0; o >>= 1) v += __shfl_down_sync(0xFFFFFFFFu, v, o);
            if ((d & 31) == 0) red[j][d >> 5] = v;
        }
        __syncthreads();
        if (d < cnt) {
            float sum = 0.f;
#pragma unroll
            for (int w8 = 0; w8 < 8; w8++) sum += red[d][w8];
            g_state_logits[i0 + s + d] = sum;
        }
        __syncthreads();
        s = e2;
    }
}

// ---------- edge pass: scalar per edge, scatter to rel_logits ----------
__global__ void __launch_bounds__(256) edge_kernel(const float* __restrict__ edge_attrs,
                                                   const int* __restrict__ edge_batch,
                                                   const int* __restrict__ src,
                                                   const int* __restrict__ dst,
                                                   const float* __restrict__ distribution,
                                                   const float* __restrict__ instr,
                                                   const float* __restrict__ w_rel) {
    __shared__ __align__(16) float attr_s[EPB][D];
    __shared__ int eb_s[EPB];
    __shared__ float red[EPB][8];
    const int d = threadIdx.x;
    const int i0 = blockIdx.x * EPB;
    const int cnt = min(EPB, N_EDGES - i0);
    for (int j = 0; j < cnt; j++) attr_s[j][d] = edge_attrs[(size_t)(i0 + j) * D + d];
    for (int j = cnt; j < EPB; j++) attr_s[j][d] = 0.f;
    if (d < cnt) eb_s[d] = edge_batch[i0 + d];
    __syncthreads();
    const float wr = w_rel[d];
    const float* __restrict__ W = g_Wet + d;
    unsigned long long acc[EPB];
#pragma unroll
    for (int j = 0; j < EPB; j++) acc[j] = 0ull;
    for (int k = 0; k < D; k += 4) {
        float w0 = __ldg(W + (size_t)k * D);
        float w1 = __ldg(W + (size_t)(k + 1) * D);
        float w2 = __ldg(W + (size_t)(k + 2) * D);
        float w3 = __ldg(W + (size_t)(k + 3) * D);
        unsigned long long wp01 = pack_f2(w0, w1);
        unsigned long long wp23 = pack_f2(w2, w3);
#pragma unroll
        for (int j = 0; j < EPB; j++) {
            const unsigned long long* ap =
                reinterpret_cast<const unsigned long long*>(&attr_s[j][k]);
            fma2(acc[j], ap[0], wp01);
            fma2(acc[j], ap[1], wp23);
        }
    }
    for (int j = 0; j < EPB; j++) {
        if (j >= cnt) break;
        float ib = instr[eb_s[j] * D + d];
        float t = ib * hsum2(acc[j]);
        float v = wr * elu1(t);
#pragma unroll
        for (int o = 16; o > 0; o >>= 1) v += __shfl_down_sync(0xFFFFFFFFu, v, o);
        if ((d & 31) == 0) red[j][d >> 5] = v;
    }
    __syncthreads();
    if (d < cnt) {
        float sum = 0.f;
#pragma unroll
        for (int w8 = 0; w8 < 8; w8++) sum += red[d][w8];
        int e = i0 + d;
        atomicAdd(&g_rel_logits[dst[e]], distribution[src[e]] * sum);
    }
}

// ---------- segment softmax + combine ----------
__device__ __forceinline__ int lower_bound_dev(const int* __restrict__ a, int n, int key) {
    int lo = 0, hi = n;
    while (lo < hi) {
        int mid = (lo + hi) >> 1;
        if (a[mid] < key) lo = mid + 1; else hi = mid;
    }
    return lo;
}

__global__ void __launch_bounds__(256) softmax_kernel(const int* __restrict__ nidx,
                                                      const float* __restrict__ rel_sim,
                                                      float* __restrict__ out) {
    const int b = blockIdx.x;
    const int t = threadIdx.x;
    __shared__ float sh[256];
    __shared__ int bounds[2];
    if (t == 0) {
        bounds[0] = lower_bound_dev(nidx, N_NODES, b);
        bounds[1] = lower_bound_dev(nidx, N_NODES, b + 1);
    }
    __syncthreads();
    const int lo = bounds[0], hi = bounds[1];
    if (hi <= lo) return;

    float m1 = -1e30f, m2 = -1e30f;
    for (int i = lo + t; i < hi; i += 256) {
        m1 = fmaxf(m1, g_state_logits[i]);
        m2 = fmaxf(m2, g_rel_logits[i]);
    }
    sh[t] = m1; __syncthreads();
    for (int o = 128; o > 0; o >>= 1) { if (t < o) sh[t] = fmaxf(sh[t], sh[t + o]); __syncthreads(); }
    m1 = sh[0]; __syncthreads();
    sh[t] = m2; __syncthreads();
    for (int o = 128; o > 0; o >>= 1) { if (t < o) sh[t] = fmaxf(sh[t], sh[t + o]); __syncthreads(); }
    m2 = sh[0]; __syncthreads();

    float s1 = 0.f, s2 = 0.f;
    for (int i = lo + t; i < hi; i += 256) {
        s1 += expf(g_state_logits[i] - m1);
        s2 += expf(g_rel_logits[i] - m2);
    }
    sh[t] = s1; __syncthreads();
    for (int o = 128; o > 0; o >>= 1) { if (t < o) sh[t] += sh[t + o]; __syncthreads(); }
    s1 = sh[0]; __syncthreads();
    sh[t] = s2; __syncthreads();
    for (int o = 128; o > 0; o >>= 1) { if (t < o) sh[t] += sh[t + o]; __syncthreads(); }
    s2 = sh[0]; __syncthreads();

    const float r = rel_sim[b];
    const float inv1 = 1.f / s1, inv2 = 1.f / s2;
    for (int i = lo + t; i < hi; i += 256) {
        float ns = expf(g_state_logits[i] - m1) * inv1;
        float nr = expf(g_rel_logits[i] - m2) * inv2;
        out[i] = r * nr + (1.f - r) * ns;
    }
}

extern "C" void kernel_launch(void* const* d_in, const int* in_sizes, int n_in,
                              void* d_out, int out_size) {
    const float* instr        = (const float*)d_in[0];   // [B, D]
    const float* distribution = (const float*)d_in[1];   // [N]
    const float* sim          = (const float*)d_in[2];   // [B, P]
    const float* rel_sim      = (const float*)d_in[3];   // [B]
    const float* node_attrs   = (const float*)d_in[4];   // [N, D]
    const float* edge_attrs   = (const float*)d_in[5];   // [E, D]
    const float* Wnp          = (const float*)d_in[6];   // [P, D, D]
    const float* We           = (const float*)d_in[7];   // [D, D]
    const float* w_node       = (const float*)d_in[8];   // [D]
    const float* w_rel        = (const float*)d_in[9];   // [D]
    const int*   node_indices = (const int*)d_in[10];    // [N] sorted
    const int*   edge_batch   = (const int*)d_in[11];    // [E]
    const int*   ei           = (const int*)d_in[12];    // [2, E]
    float* out = (float*)d_out;

    prep_kernel<<<(P * D * D + D * D + 255) / 256, 256>>>(Wnp, We);
    weff_kernel<<<(D * D) / 256, 256>>>(sim);
    zero_kernel<<<(N_NODES + 255) / 256, 256>>>();
    node_kernel<<<(N_NODES + NPB - 1) / NPB, 256>>>(node_attrs, node_indices, instr, w_node);
    edge_kernel<<<(N_EDGES + EPB - 1) / EPB, 256>>>(edge_attrs, edge_batch, ei, ei + N_EDGES,
                                                    distribution, instr, w_rel);
    softmax_kernel<<<B_GR, 256>>>(node_indices, rel_sim, out);
}

// round 2
// speedup vs baseline: 1.8814x; 1.8814x over previous
#include <cuda_runtime.h>

#define D 256
#define P 8
#define B_GR 128
#define N_NODES 50000
#define N_EDGES 300000
#define TPB 32
#define NBLK_EDGE ((N_EDGES + TPB - 1) / TPB)
#define NBLK_NODE ((N_NODES + TPB - 1) / TPB)

typedef unsigned long long ull;

__device__ __align__(16) float g_Wpt[P * D * D];     // [p][e][d] = W[p][d][e]
__device__ __align__(16) float g_Wet[D * D];         // [k][d] = W_edge[d][k]
__device__ __align__(16) float g_Weff[B_GR * D * D]; // [b][e][d]
__device__ float g_state_logits[N_NODES];
__device__ float g_rel_logits[N_NODES];

// ---------- packed f32x2 helpers ----------
__device__ __forceinline__ ull pack_f2(float lo, float hi) {
    ull r;
    asm("mov.b64 %0, {%1, %2};" : "=l"(r) : "f"(lo), "f"(hi));
    return r;
}
__device__ __forceinline__ void fma2(ull& acc, ull a, ull b) {
    asm("fma.rn.f32x2 %0, %1, %2, %0;" : "+l"(acc) : "l"(a), "l"(b));
}
__device__ __forceinline__ void unpack_f2(ull v, float& lo, float& hi) {
    asm("mov.b64 {%0, %1}, %2;" : "=f"(lo), "=f"(hi) : "l"(v));
}
__device__ __forceinline__ float elu1(float x) { return x > 0.f ? x : expm1f(x); }

// ---------- prep: transposes ----------
__global__ void prep_kernel(const float* __restrict__ Wnp, const float* __restrict__ We) {
    int tid = blockIdx.x * blockDim.x + threadIdx.x;
    if (tid < P * D * D) {
        int p = tid >> 16;
        int rem = tid & 0xFFFF;
        int e = rem >> 8;
        int d = rem & 0xFF;
        g_Wpt[tid] = Wnp[p * (D * D) + d * D + e];
    } else if (tid < P * D * D + D * D) {
        int r = tid - P * D * D;
        int k = r >> 8;
        int d = r & 0xFF;
        g_Wet[r] = We[d * D + k];
    }
}

// ---------- W_eff[b] = sum_p sim[b][p] * Wpt[p] ----------
__global__ void __launch_bounds__(256) weff_kernel(const float* __restrict__ sim) {
    __shared__ float wpt_s[P][256];
    __shared__ float sim_s[B_GR * P];
    const int t = threadIdx.x;
    const int base = blockIdx.x * 256;
#pragma unroll
    for (int p = 0; p < P; p++) wpt_s[p][t] = g_Wpt[p * (D * D) + base + t];
    for (int i = t; i < B_GR * P; i += 256) sim_s[i] = sim[i];
    __syncthreads();
    for (int b = 0; b < B_GR; b++) {
        float a = 0.f;
#pragma unroll
        for (int p = 0; p < P; p++) a = fmaf(sim_s[b * P + p], wpt_s[p][t], a);
        g_Weff[(size_t)b * (D * D) + base + t] = a;
    }
}

__global__ void zero_kernel() {
    int i = blockIdx.x * blockDim.x + threadIdx.x;
    if (i < N_NODES) g_rel_logits[i] = 0.f;
}

// ---------- fused node+edge GEMV-scoring kernel ----------
// 256 threads = 64 d-groups (4 d's, two f32x2 pairs) x 4 row-groups (8 rows).
__global__ void __launch_bounds__(256) main_kernel(
    const float* __restrict__ node_attrs, const int* __restrict__ node_indices,
    const float* __restrict__ edge_attrs, const int* __restrict__ edge_batch,
    const int* __restrict__ src, const int* __restrict__ dst,
    const float* __restrict__ distribution, const float* __restrict__ instr,
    const float* __restrict__ w_node, const float* __restrict__ w_rel) {
    __shared__ __align__(16) float attr_s[TPB][D];
    __shared__ int b_s[TPB];
    __shared__ float red[TPB][2];

    const int t = threadIdx.x;
    const int dg = t & 63;
    const int rg = t >> 6;
    const int d0 = dg * 4;
    const int rowbase = rg * 8;

    const bool isEdge = blockIdx.x < NBLK_EDGE;
    const int i0 = isEdge ? blockIdx.x * TPB : (blockIdx.x - NBLK_EDGE) * TPB;
    const int limit = isEdge ? N_EDGES : N_NODES;
    const int cnt = min(TPB, limit - i0);
    const float* __restrict__ gattr = isEdge ? edge_attrs : node_attrs;

    // stage attr tile (zero-padded)
    {
        const float4* ga4 = (const float4*)(gattr + (size_t)i0 * D);
        float4* as4 = (float4*)attr_s;
        const int nv = cnt * (D / 4);
        for (int idx = t; idx < TPB * (D / 4); idx += 256)
            as4[idx] = (idx < nv) ? __ldg(ga4 + idx) : make_float4(0.f, 0.f, 0.f, 0.f);
    }
    if (t < TPB) b_s[t] = (t < cnt) ? (isEdge ? edge_batch[i0 + t] : node_indices[i0 + t]) : -1;
    __syncthreads();

    ull acc[8][2];
#pragma unroll
    for (int j = 0; j < 8; j++) { acc[j][0] = 0ull; acc[j][1] = 0ull; }

    const float* Wbase;
    bool fast;
    if (isEdge) {
        Wbase = g_Wet;
        fast = true;
    } else {
        int bfirst = b_s[0];
        fast = (cnt == TPB) && (bfirst == b_s[TPB - 1]);
        Wbase = g_Weff + (size_t)bfirst * (D * D);
    }

    if (fast) {
        const float* attrRow = &attr_s[rowbase][0];
        const ulonglong2* __restrict__ Wv = (const ulonglong2*)(Wbase + d0);
#pragma unroll 2
        for (int k = 0; k < D; k += 2) {
            ulonglong2 wa = __ldg(Wv + (size_t)k * (D / 4));
            ulonglong2 wb = __ldg(Wv + (size_t)(k + 1) * (D / 4));
#pragma unroll
            for (int j = 0; j < 8; j++) {
                float2 a = *(const float2*)(attrRow + j * D + k);
                ull a0 = pack_f2(a.x, a.x);
                ull a1 = pack_f2(a.y, a.y);
                fma2(acc[j][0], a0, wa.x);
                fma2(acc[j][1], a0, wa.y);
                fma2(acc[j][0], a1, wb.x);
                fma2(acc[j][1], a1, wb.y);
            }
        }
    } else {
        // graph boundary inside tile (rare): per-row W
#pragma unroll 1
        for (int j = 0; j < 8; j++) {
            int row = rowbase + j;
            if (row >= cnt) break;
            const ulonglong2* __restrict__ Wv =
                (const ulonglong2*)(g_Weff + (size_t)b_s[row] * (D * D) + d0);
            ull c0 = 0ull, c1 = 0ull;
            for (int k = 0; k < D; k += 2) {
                ulonglong2 wa = __ldg(Wv + (size_t)k * (D / 4));
                ulonglong2 wb = __ldg(Wv + (size_t)(k + 1) * (D / 4));
                float2 a = *(const float2*)(&attr_s[row][k]);
                ull a0 = pack_f2(a.x, a.x);
                ull a1 = pack_f2(a.y, a.y);
                fma2(c0, a0, wa.x);
                fma2(c1, a0, wa.y);
                fma2(c0, a1, wb.x);
                fma2(c1, a1, wb.y);
            }
            acc[j][0] = c0;
            acc[j][1] = c1;
        }
    }

    // epilogue: t = instr[b][d] * acc; v = w . elu(t); reduce per row
    const float* wvec = isEdge ? w_rel : w_node;
    const float4 wr4 = __ldg((const float4*)(wvec + d0));
    const int half = (t >> 5) & 1;
#pragma unroll
    for (int j = 0; j < 8; j++) {
        int row = rowbase + j;
        float local = 0.f;
        if (row < cnt) {
            int b = b_s[row];
            float4 ins = __ldg((const float4*)(instr + b * D + d0));
            float x0, x1, x2, x3;
            unpack_f2(acc[j][0], x0, x1);
            unpack_f2(acc[j][1], x2, x3);
            local = wr4.x * elu1(ins.x * x0) + wr4.y * elu1(ins.y * x1) +
                    wr4.z * elu1(ins.z * x2) + wr4.w * elu1(ins.w * x3);
        }
#pragma unroll
        for (int o = 16; o > 0; o >>= 1) local += __shfl_down_sync(0xFFFFFFFFu, local, o);
        if ((t & 31) == 0) red[row][half] = local;
    }
    __syncthreads();
    if (t < cnt) {
        float v = red[t][0] + red[t][1];
        int g = i0 + t;
        if (isEdge) {
            atomicAdd(&g_rel_logits[dst[g]], distribution[src[g]] * v);
        } else {
            g_state_logits[g] = v;
        }
    }
}

// ---------- segment softmax + combine ----------
__device__ __forceinline__ int lower_bound_dev(const int* __restrict__ a, int n, int key) {
    int lo = 0, hi = n;
    while (lo < hi) {
        int mid = (lo + hi) >> 1;
        if (a[mid] < key) lo = mid + 1; else hi = mid;
    }
    return lo;
}

__global__ void __launch_bounds__(256) softmax_kernel(const int* __restrict__ nidx,
                                                      const float* __restrict__ rel_sim,
                                                      float* __restrict__ out) {
    const int b = blockIdx.x;
    const int t = threadIdx.x;
    __shared__ float sh[256];
    __shared__ int bounds[2];
    if (t == 0) {
        bounds[0] = lower_bound_dev(nidx, N_NODES, b);
        bounds[1] = lower_bound_dev(nidx, N_NODES, b + 1);
    }
    __syncthreads();
    const int lo = bounds[0], hi = bounds[1];
    if (hi <= lo) return;

    float m1 = -1e30f, m2 = -1e30f;
    for (int i = lo + t; i < hi; i += 256) {
        m1 = fmaxf(m1, g_state_logits[i]);
        m2 = fmaxf(m2, g_rel_logits[i]);
    }
    sh[t] = m1; __syncthreads();
    for (int o = 128; o > 0; o >>= 1) { if (t < o) sh[t] = fmaxf(sh[t], sh[t + o]); __syncthreads(); }
    m1 = sh[0]; __syncthreads();
    sh[t] = m2; __syncthreads();
    for (int o = 128; o > 0; o >>= 1) { if (t < o) sh[t] = fmaxf(sh[t], sh[t + o]); __syncthreads(); }
    m2 = sh[0]; __syncthreads();

    float s1 = 0.f, s2 = 0.f;
    for (int i = lo + t; i < hi; i += 256) {
        s1 += expf(g_state_logits[i] - m1);
        s2 += expf(g_rel_logits[i] - m2);
    }
    sh[t] = s1; __syncthreads();
    for (int o = 128; o > 0; o >>= 1) { if (t < o) sh[t] += sh[t + o]; __syncthreads(); }
    s1 = sh[0]; __syncthreads();
    sh[t] = s2; __syncthreads();
    for (int o = 128; o > 0; o >>= 1) { if (t < o) sh[t] += sh[t + o]; __syncthreads(); }
    s2 = sh[0]; __syncthreads();

    const float r = rel_sim[b];
    const float inv1 = 1.f / s1, inv2 = 1.f / s2;
    for (int i = lo + t; i < hi; i += 256) {
        float ns = expf(g_state_logits[i] - m1) * inv1;
        float nr = expf(g_rel_logits[i] - m2) * inv2;
        out[i] = r * nr + (1.f - r) * ns;
    }
}

extern "C" void kernel_launch(void* const* d_in, const int* in_sizes, int n_in,
                              void* d_out, int out_size) {
    const float* instr        = (const float*)d_in[0];
    const float* distribution = (const float*)d_in[1];
    const float* sim          = (const float*)d_in[2];
    const float* rel_sim      = (const float*)d_in[3];
    const float* node_attrs   = (const float*)d_in[4];
    const float* edge_attrs   = (const float*)d_in[5];
    const float* Wnp          = (const float*)d_in[6];
    const float* We           = (const float*)d_in[7];
    const float* w_node       = (const float*)d_in[8];
    const float* w_rel        = (const float*)d_in[9];
    const int*   node_indices = (const int*)d_in[10];
    const int*   edge_batch   = (const int*)d_in[11];
    const int*   ei           = (const int*)d_in[12];
    float* out = (float*)d_out;

    prep_kernel<<<(P * D * D + D * D + 255) / 256, 256>>>(Wnp, We);
    weff_kernel<<<(D * D) / 256, 256>>>(sim);
    zero_kernel<<<(N_NODES + 255) / 256, 256>>>();
    main_kernel<<<NBLK_EDGE + NBLK_NODE, 256>>>(node_attrs, node_indices, edge_attrs,
                                                edge_batch, ei, ei + N_EDGES, distribution,
                                                instr, w_node, w_rel);
    softmax_kernel<<<B_GR, 256>>>(node_indices, rel_sim, out);
}